// round 4
// baseline (speedup 1.0000x reference)
#include <cuda_runtime.h>
#include <cfloat>

#define NQ      4096
#define D_MODEL 320
#define HEADS   8
#define DH      40
#define KT      32     // key tile
#define QT      128    // queries per block (1 thread per query)

// Scratch (static: no allocation allowed in kernel_launch)
__device__ float g_q[NQ * D_MODEL];
__device__ float g_k[NQ * D_MODEL];
__device__ float g_v[NQ * D_MODEL];
__device__ float g_ao[NQ * D_MODEL];
__device__ unsigned int g_bits[NQ];

// ---------------------------------------------------------------------------
// SGEMM: C[M,N] = A[M,K] @ B[K,N] (+ bias). 64x64 block tile, 16 K-tile,
// 256 threads, 4x4 register micro-tile. M,N,K assumed multiples of tile dims
// (4096/320/320 all are).
// ---------------------------------------------------------------------------
__global__ void __launch_bounds__(256) gemm_kernel(
    const float* __restrict__ A, const float* __restrict__ B,
    const float* __restrict__ bias, float* __restrict__ C,
    int M, int N, int K)
{
    __shared__ float As[16][64];   // transposed A tile: As[k][m]
    __shared__ float Bs[16][64];   // Bs[k][n]

    const int tid  = threadIdx.x;
    const int tx   = tid & 15;     // 0..15 -> 4 cols each
    const int ty   = tid >> 4;     // 0..15 -> 4 rows each
    const int row0 = blockIdx.y * 64;
    const int col0 = blockIdx.x * 64;

    const int a_m = tid >> 2;        // 0..63
    const int a_k = (tid & 3) * 4;   // 0,4,8,12
    const int b_k = tid >> 4;        // 0..15
    const int b_n = (tid & 15) * 4;  // 0..60

    float acc[4][4] = {};

    for (int k0 = 0; k0 < K; k0 += 16) {
        float4 av = *(const float4*)&A[(row0 + a_m) * K + k0 + a_k];
        As[a_k + 0][a_m] = av.x;
        As[a_k + 1][a_m] = av.y;
        As[a_k + 2][a_m] = av.z;
        As[a_k + 3][a_m] = av.w;
        *(float4*)&Bs[b_k][b_n] = *(const float4*)&B[(k0 + b_k) * N + col0 + b_n];
        __syncthreads();

        #pragma unroll
        for (int kk = 0; kk < 16; kk++) {
            float4 af = *(const float4*)&As[kk][ty * 4];
            float4 bf = *(const float4*)&Bs[kk][tx * 4];
            acc[0][0] += af.x * bf.x; acc[0][1] += af.x * bf.y;
            acc[0][2] += af.x * bf.z; acc[0][3] += af.x * bf.w;
            acc[1][0] += af.y * bf.x; acc[1][1] += af.y * bf.y;
            acc[1][2] += af.y * bf.z; acc[1][3] += af.y * bf.w;
            acc[2][0] += af.z * bf.x; acc[2][1] += af.z * bf.y;
            acc[2][2] += af.z * bf.z; acc[2][3] += af.z * bf.w;
            acc[3][0] += af.w * bf.x; acc[3][1] += af.w * bf.y;
            acc[3][2] += af.w * bf.z; acc[3][3] += af.w * bf.w;
        }
        __syncthreads();
    }

    #pragma unroll
    for (int i = 0; i < 4; i++) {
        const int r = row0 + ty * 4 + i;
        #pragma unroll
        for (int j = 0; j < 4; j++) {
            const int c = col0 + tx * 4 + j;
            float val = acc[i][j];
            if (bias) val += bias[c];
            C[r * N + c] = val;
        }
    }
}

// ---------------------------------------------------------------------------
// Pack guidance mask -> 3-bit phase occupancy per token.
// mask_sim[i][j] != 0  <=>  (bits[i] & bits[j]) != 0
// ---------------------------------------------------------------------------
__global__ void mask_kernel(const float* __restrict__ g)
{
    int i = blockIdx.x * blockDim.x + threadIdx.x;
    if (i < NQ) {
        unsigned int b = 0;
        if (g[0 * NQ + i] > 0.5f) b |= 1u;
        if (g[1 * NQ + i] > 0.5f) b |= 2u;
        if (g[2 * NQ + i] > 0.5f) b |= 4u;
        g_bits[i] = b;
    }
}

// ---------------------------------------------------------------------------
// Flash-style masked attention. One thread owns one query row of one head.
// Masked score = -FLT_MAX (NOT -inf): reproduces jax softmax's uniform
// distribution for fully-masked rows (exp(0)=1 everywhere).
// ---------------------------------------------------------------------------
__global__ void __launch_bounds__(QT) attn_kernel()
{
    const int h    = blockIdx.y;
    const int qi   = blockIdx.x * QT + threadIdx.x;
    const int base = h * DH;

    __shared__ float ks[KT][DH];
    __shared__ float vs[KT][DH];
    __shared__ unsigned int kb[KT];

    const float scale = 0.15811388300841897f;  // 40^-0.5

    float qr[DH];
    #pragma unroll
    for (int d = 0; d < DH; d++)
        qr[d] = g_q[qi * D_MODEL + base + d] * scale;
    const unsigned int qb = g_bits[qi];

    float m = -FLT_MAX;
    float l = 0.0f;
    float acc[DH];
    #pragma unroll
    for (int d = 0; d < DH; d++) acc[d] = 0.0f;

    for (int kt = 0; kt < NQ; kt += KT) {
        __syncthreads();
        #pragma unroll
        for (int t = 0; t < (KT * DH) / QT; t++) {
            int idx = threadIdx.x + t * QT;
            int j = idx / DH;
            int d = idx - j * DH;
            ks[j][d] = g_k[(kt + j) * D_MODEL + base + d];
            vs[j][d] = g_v[(kt + j) * D_MODEL + base + d];
        }
        if (threadIdx.x < KT) kb[threadIdx.x] = g_bits[kt + threadIdx.x];
        __syncthreads();

        float s[KT];
        float mt = m;
        #pragma unroll
        for (int j = 0; j < KT; j++) {
            const float4* kp = (const float4*)&ks[j][0];
            float a0 = 0.f, a1 = 0.f, a2 = 0.f, a3 = 0.f;
            #pragma unroll
            for (int t = 0; t < DH / 4; t++) {
                float4 kk = kp[t];
                a0 += qr[4 * t + 0] * kk.x;
                a1 += qr[4 * t + 1] * kk.y;
                a2 += qr[4 * t + 2] * kk.z;
                a3 += qr[4 * t + 3] * kk.w;
            }
            float sv = (a0 + a1) + (a2 + a3);
            sv = (qb & kb[j]) ? sv : -FLT_MAX;
            s[j] = sv;
            mt = fmaxf(mt, sv);
        }

        // corr: exp(0)=1 when both -FLT_MAX; exp(-huge)=0 once real scores seen
        const float corr = __expf(m - mt);
        m = mt;
        l *= corr;
        #pragma unroll
        for (int d = 0; d < DH; d++) acc[d] *= corr;

        #pragma unroll
        for (int j = 0; j < KT; j++) {
            float p = __expf(s[j] - mt);
            l += p;
            const float4* vp = (const float4*)&vs[j][0];
            #pragma unroll
            for (int t = 0; t < DH / 4; t++) {
                float4 vv = vp[t];
                acc[4 * t + 0] += p * vv.x;
                acc[4 * t + 1] += p * vv.y;
                acc[4 * t + 2] += p * vv.z;
                acc[4 * t + 3] += p * vv.w;
            }
        }
    }

    const float inv = 1.0f / l;   // l >= 1 always (uniform fallback => l = 4096)
    #pragma unroll
    for (int d = 0; d < DH; d++)
        g_ao[qi * D_MODEL + base + d] = acc[d] * inv;
}

// ---------------------------------------------------------------------------
extern "C" void kernel_launch(void* const* d_in, const int* in_sizes, int n_in,
                              void* d_out, int out_size)
{
    const float* x   = (const float*)d_in[0];
    const float* gm  = (const float*)d_in[1];
    const float* Wq  = (const float*)d_in[2];
    const float* Wk  = (const float*)d_in[3];
    const float* Wv  = (const float*)d_in[4];
    const float* Wo  = (const float*)d_in[5];
    const float* bo  = (const float*)d_in[6];
    float* out = (float*)d_out;

    float *q, *k, *v, *ao;
    cudaGetSymbolAddress((void**)&q,  g_q);
    cudaGetSymbolAddress((void**)&k,  g_k);
    cudaGetSymbolAddress((void**)&v,  g_v);
    cudaGetSymbolAddress((void**)&ao, g_ao);

    dim3 gemm_grid(D_MODEL / 64, NQ / 64);  // (5, 64)

    gemm_kernel<<<gemm_grid, 256>>>(x, Wq, nullptr, q, NQ, D_MODEL, D_MODEL);
    gemm_kernel<<<gemm_grid, 256>>>(x, Wk, nullptr, k, NQ, D_MODEL, D_MODEL);
    gemm_kernel<<<gemm_grid, 256>>>(x, Wv, nullptr, v, NQ, D_MODEL, D_MODEL);

    mask_kernel<<<NQ / 256, 256>>>(gm);

    attn_kernel<<<dim3(NQ / QT, HEADS), QT>>>();

    gemm_kernel<<<gemm_grid, 256>>>(ao, Wo, bo, out, NQ, D_MODEL, D_MODEL);
}

// round 5
// speedup vs baseline: 1.0040x; 1.0040x over previous
#include <cuda_runtime.h>
#include <cfloat>

#define NQ      4096
#define D_MODEL 320
#define HEADS   8
#define DH      40
#define KT      32     // key tile
#define QT      128    // queries per block (1 thread per query)

// Scratch (static: no allocation allowed in kernel_launch)
__device__ float g_q[NQ * D_MODEL];
__device__ float g_k[NQ * D_MODEL];
__device__ float g_v[NQ * D_MODEL];
__device__ float g_ao[NQ * D_MODEL];
__device__ unsigned int g_bits[NQ];

// ---------------------------------------------------------------------------
// SGEMM: C[M,N] = A[M,K] @ B[K,N] (+ bias). 64x64 block tile, 16 K-tile,
// 256 threads, 4x4 register micro-tile. M,N,K assumed multiples of tile dims
// (4096/320/320 all are).
// ---------------------------------------------------------------------------
__global__ void __launch_bounds__(256) gemm_kernel(
    const float* __restrict__ A, const float* __restrict__ B,
    const float* __restrict__ bias, float* __restrict__ C,
    int M, int N, int K)
{
    __shared__ float As[16][64];   // transposed A tile: As[k][m]
    __shared__ float Bs[16][64];   // Bs[k][n]

    const int tid  = threadIdx.x;
    const int tx   = tid & 15;     // 0..15 -> 4 cols each
    const int ty   = tid >> 4;     // 0..15 -> 4 rows each
    const int row0 = blockIdx.y * 64;
    const int col0 = blockIdx.x * 64;

    const int a_m = tid >> 2;        // 0..63
    const int a_k = (tid & 3) * 4;   // 0,4,8,12
    const int b_k = tid >> 4;        // 0..15
    const int b_n = (tid & 15) * 4;  // 0..60

    float acc[4][4] = {};

    for (int k0 = 0; k0 < K; k0 += 16) {
        float4 av = *(const float4*)&A[(row0 + a_m) * K + k0 + a_k];
        As[a_k + 0][a_m] = av.x;
        As[a_k + 1][a_m] = av.y;
        As[a_k + 2][a_m] = av.z;
        As[a_k + 3][a_m] = av.w;
        *(float4*)&Bs[b_k][b_n] = *(const float4*)&B[(k0 + b_k) * N + col0 + b_n];
        __syncthreads();

        #pragma unroll
        for (int kk = 0; kk < 16; kk++) {
            float4 af = *(const float4*)&As[kk][ty * 4];
            float4 bf = *(const float4*)&Bs[kk][tx * 4];
            acc[0][0] += af.x * bf.x; acc[0][1] += af.x * bf.y;
            acc[0][2] += af.x * bf.z; acc[0][3] += af.x * bf.w;
            acc[1][0] += af.y * bf.x; acc[1][1] += af.y * bf.y;
            acc[1][2] += af.y * bf.z; acc[1][3] += af.y * bf.w;
            acc[2][0] += af.z * bf.x; acc[2][1] += af.z * bf.y;
            acc[2][2] += af.z * bf.z; acc[2][3] += af.z * bf.w;
            acc[3][0] += af.w * bf.x; acc[3][1] += af.w * bf.y;
            acc[3][2] += af.w * bf.z; acc[3][3] += af.w * bf.w;
        }
        __syncthreads();
    }

    #pragma unroll
    for (int i = 0; i < 4; i++) {
        const int r = row0 + ty * 4 + i;
        #pragma unroll
        for (int j = 0; j < 4; j++) {
            const int c = col0 + tx * 4 + j;
            float val = acc[i][j];
            if (bias) val += bias[c];
            C[r * N + c] = val;
        }
    }
}

// ---------------------------------------------------------------------------
// Pack guidance mask -> 3-bit phase occupancy per token.
// mask_sim[i][j] != 0  <=>  (bits[i] & bits[j]) != 0
// ---------------------------------------------------------------------------
__global__ void mask_kernel(const float* __restrict__ g)
{
    int i = blockIdx.x * blockDim.x + threadIdx.x;
    if (i < NQ) {
        unsigned int b = 0;
        if (g[0 * NQ + i] > 0.5f) b |= 1u;
        if (g[1 * NQ + i] > 0.5f) b |= 2u;
        if (g[2 * NQ + i] > 0.5f) b |= 4u;
        g_bits[i] = b;
    }
}

// ---------------------------------------------------------------------------
// Flash-style masked attention. One thread owns one query row of one head.
// Masked score = -FLT_MAX (NOT -inf): reproduces jax softmax's uniform
// distribution for fully-masked rows (exp(0)=1 everywhere).
// ---------------------------------------------------------------------------
__global__ void __launch_bounds__(QT) attn_kernel()
{
    const int h    = blockIdx.y;
    const int qi   = blockIdx.x * QT + threadIdx.x;
    const int base = h * DH;

    __shared__ float ks[KT][DH];
    __shared__ float vs[KT][DH];
    __shared__ unsigned int kb[KT];

    const float scale = 0.15811388300841897f;  // 40^-0.5

    float qr[DH];
    #pragma unroll
    for (int d = 0; d < DH; d++)
        qr[d] = g_q[qi * D_MODEL + base + d] * scale;
    const unsigned int qb = g_bits[qi];

    float m = -FLT_MAX;
    float l = 0.0f;
    float acc[DH];
    #pragma unroll
    for (int d = 0; d < DH; d++) acc[d] = 0.0f;

    for (int kt = 0; kt < NQ; kt += KT) {
        __syncthreads();
        #pragma unroll
        for (int t = 0; t < (KT * DH) / QT; t++) {
            int idx = threadIdx.x + t * QT;
            int j = idx / DH;
            int d = idx - j * DH;
            ks[j][d] = g_k[(kt + j) * D_MODEL + base + d];
            vs[j][d] = g_v[(kt + j) * D_MODEL + base + d];
        }
        if (threadIdx.x < KT) kb[threadIdx.x] = g_bits[kt + threadIdx.x];
        __syncthreads();

        float s[KT];
        float mt = m;
        #pragma unroll
        for (int j = 0; j < KT; j++) {
            const float4* kp = (const float4*)&ks[j][0];
            float a0 = 0.f, a1 = 0.f, a2 = 0.f, a3 = 0.f;
            #pragma unroll
            for (int t = 0; t < DH / 4; t++) {
                float4 kk = kp[t];
                a0 += qr[4 * t + 0] * kk.x;
                a1 += qr[4 * t + 1] * kk.y;
                a2 += qr[4 * t + 2] * kk.z;
                a3 += qr[4 * t + 3] * kk.w;
            }
            float sv = (a0 + a1) + (a2 + a3);
            sv = (qb & kb[j]) ? sv : -FLT_MAX;
            s[j] = sv;
            mt = fmaxf(mt, sv);
        }

        // corr: exp(0)=1 when both -FLT_MAX; exp(-huge)=0 once real scores seen
        const float corr = __expf(m - mt);
        m = mt;
        l *= corr;
        #pragma unroll
        for (int d = 0; d < DH; d++) acc[d] *= corr;

        #pragma unroll
        for (int j = 0; j < KT; j++) {
            float p = __expf(s[j] - mt);
            l += p;
            const float4* vp = (const float4*)&vs[j][0];
            #pragma unroll
            for (int t = 0; t < DH / 4; t++) {
                float4 vv = vp[t];
                acc[4 * t + 0] += p * vv.x;
                acc[4 * t + 1] += p * vv.y;
                acc[4 * t + 2] += p * vv.z;
                acc[4 * t + 3] += p * vv.w;
            }
        }
    }

    const float inv = 1.0f / l;   // l >= 1 always (uniform fallback => l = 4096)
    #pragma unroll
    for (int d = 0; d < DH; d++)
        g_ao[qi * D_MODEL + base + d] = acc[d] * inv;
}

// ---------------------------------------------------------------------------
extern "C" void kernel_launch(void* const* d_in, const int* in_sizes, int n_in,
                              void* d_out, int out_size)
{
    const float* x   = (const float*)d_in[0];
    const float* gm  = (const float*)d_in[1];
    const float* Wq  = (const float*)d_in[2];
    const float* Wk  = (const float*)d_in[3];
    const float* Wv  = (const float*)d_in[4];
    const float* Wo  = (const float*)d_in[5];
    const float* bo  = (const float*)d_in[6];
    float* out = (float*)d_out;

    float *q, *k, *v, *ao;
    cudaGetSymbolAddress((void**)&q,  g_q);
    cudaGetSymbolAddress((void**)&k,  g_k);
    cudaGetSymbolAddress((void**)&v,  g_v);
    cudaGetSymbolAddress((void**)&ao, g_ao);

    dim3 gemm_grid(D_MODEL / 64, NQ / 64);  // (5, 64)

    gemm_kernel<<<gemm_grid, 256>>>(x, Wq, nullptr, q, NQ, D_MODEL, D_MODEL);
    gemm_kernel<<<gemm_grid, 256>>>(x, Wk, nullptr, k, NQ, D_MODEL, D_MODEL);
    gemm_kernel<<<gemm_grid, 256>>>(x, Wv, nullptr, v, NQ, D_MODEL, D_MODEL);

    mask_kernel<<<NQ / 256, 256>>>(gm);

    attn_kernel<<<dim3(NQ / QT, HEADS), QT>>>();

    gemm_kernel<<<gemm_grid, 256>>>(ao, Wo, bo, out, NQ, D_MODEL, D_MODEL);
}

// round 6
// speedup vs baseline: 1.0046x; 1.0005x over previous
#include <cuda_runtime.h>
#include <cfloat>

#define NQ      4096
#define D_MODEL 320
#define HEADS   8
#define DH      40
#define KT      32     // key tile
#define QT      128    // queries per block (1 thread per query)

// Scratch (static: no allocation allowed in kernel_launch)
__device__ float g_q[NQ * D_MODEL];
__device__ float g_k[NQ * D_MODEL];
__device__ float g_v[NQ * D_MODEL];
__device__ float g_ao[NQ * D_MODEL];
__device__ unsigned int g_bits[NQ];

// ---------------------------------------------------------------------------
// SGEMM: C[M,N] = A[M,K] @ B[K,N] (+ bias). 64x64 block tile, 16 K-tile,
// 256 threads, 4x4 register micro-tile. M,N,K assumed multiples of tile dims
// (4096/320/320 all are).
// ---------------------------------------------------------------------------
__global__ void __launch_bounds__(256) gemm_kernel(
    const float* __restrict__ A, const float* __restrict__ B,
    const float* __restrict__ bias, float* __restrict__ C,
    int M, int N, int K)
{
    __shared__ float As[16][64];   // transposed A tile: As[k][m]
    __shared__ float Bs[16][64];   // Bs[k][n]

    const int tid  = threadIdx.x;
    const int tx   = tid & 15;     // 0..15 -> 4 cols each
    const int ty   = tid >> 4;     // 0..15 -> 4 rows each
    const int row0 = blockIdx.y * 64;
    const int col0 = blockIdx.x * 64;

    const int a_m = tid >> 2;        // 0..63
    const int a_k = (tid & 3) * 4;   // 0,4,8,12
    const int b_k = tid >> 4;        // 0..15
    const int b_n = (tid & 15) * 4;  // 0..60

    float acc[4][4] = {};

    for (int k0 = 0; k0 < K; k0 += 16) {
        float4 av = *(const float4*)&A[(row0 + a_m) * K + k0 + a_k];
        As[a_k + 0][a_m] = av.x;
        As[a_k + 1][a_m] = av.y;
        As[a_k + 2][a_m] = av.z;
        As[a_k + 3][a_m] = av.w;
        *(float4*)&Bs[b_k][b_n] = *(const float4*)&B[(k0 + b_k) * N + col0 + b_n];
        __syncthreads();

        #pragma unroll
        for (int kk = 0; kk < 16; kk++) {
            float4 af = *(const float4*)&As[kk][ty * 4];
            float4 bf = *(const float4*)&Bs[kk][tx * 4];
            acc[0][0] += af.x * bf.x; acc[0][1] += af.x * bf.y;
            acc[0][2] += af.x * bf.z; acc[0][3] += af.x * bf.w;
            acc[1][0] += af.y * bf.x; acc[1][1] += af.y * bf.y;
            acc[1][2] += af.y * bf.z; acc[1][3] += af.y * bf.w;
            acc[2][0] += af.z * bf.x; acc[2][1] += af.z * bf.y;
            acc[2][2] += af.z * bf.z; acc[2][3] += af.z * bf.w;
            acc[3][0] += af.w * bf.x; acc[3][1] += af.w * bf.y;
            acc[3][2] += af.w * bf.z; acc[3][3] += af.w * bf.w;
        }
        __syncthreads();
    }

    #pragma unroll
    for (int i = 0; i < 4; i++) {
        const int r = row0 + ty * 4 + i;
        #pragma unroll
        for (int j = 0; j < 4; j++) {
            const int c = col0 + tx * 4 + j;
            float val = acc[i][j];
            if (bias) val += bias[c];
            C[r * N + c] = val;
        }
    }
}

// ---------------------------------------------------------------------------
// Pack guidance mask -> 3-bit phase occupancy per token.
// mask_sim[i][j] != 0  <=>  (bits[i] & bits[j]) != 0
// ---------------------------------------------------------------------------
__global__ void mask_kernel(const float* __restrict__ g)
{
    int i = blockIdx.x * blockDim.x + threadIdx.x;
    if (i < NQ) {
        unsigned int b = 0;
        if (g[0 * NQ + i] > 0.5f) b |= 1u;
        if (g[1 * NQ + i] > 0.5f) b |= 2u;
        if (g[2 * NQ + i] > 0.5f) b |= 4u;
        g_bits[i] = b;
    }
}

// ---------------------------------------------------------------------------
// Flash-style masked attention. One thread owns one query row of one head.
// Masked score = -FLT_MAX (NOT -inf): reproduces jax softmax's uniform
// distribution for fully-masked rows (exp(0)=1 everywhere).
// ---------------------------------------------------------------------------
__global__ void __launch_bounds__(QT) attn_kernel()
{
    const int h    = blockIdx.y;
    const int qi   = blockIdx.x * QT + threadIdx.x;
    const int base = h * DH;

    __shared__ float ks[KT][DH];
    __shared__ float vs[KT][DH];
    __shared__ unsigned int kb[KT];

    const float scale = 0.15811388300841897f;  // 40^-0.5

    float qr[DH];
    #pragma unroll
    for (int d = 0; d < DH; d++)
        qr[d] = g_q[qi * D_MODEL + base + d] * scale;
    const unsigned int qb = g_bits[qi];

    float m = -FLT_MAX;
    float l = 0.0f;
    float acc[DH];
    #pragma unroll
    for (int d = 0; d < DH; d++) acc[d] = 0.0f;

    for (int kt = 0; kt < NQ; kt += KT) {
        __syncthreads();
        #pragma unroll
        for (int t = 0; t < (KT * DH) / QT; t++) {
            int idx = threadIdx.x + t * QT;
            int j = idx / DH;
            int d = idx - j * DH;
            ks[j][d] = g_k[(kt + j) * D_MODEL + base + d];
            vs[j][d] = g_v[(kt + j) * D_MODEL + base + d];
        }
        if (threadIdx.x < KT) kb[threadIdx.x] = g_bits[kt + threadIdx.x];
        __syncthreads();

        float s[KT];
        float mt = m;
        #pragma unroll
        for (int j = 0; j < KT; j++) {
            const float4* kp = (const float4*)&ks[j][0];
            float a0 = 0.f, a1 = 0.f, a2 = 0.f, a3 = 0.f;
            #pragma unroll
            for (int t = 0; t < DH / 4; t++) {
                float4 kk = kp[t];
                a0 += qr[4 * t + 0] * kk.x;
                a1 += qr[4 * t + 1] * kk.y;
                a2 += qr[4 * t + 2] * kk.z;
                a3 += qr[4 * t + 3] * kk.w;
            }
            float sv = (a0 + a1) + (a2 + a3);
            sv = (qb & kb[j]) ? sv : -FLT_MAX;
            s[j] = sv;
            mt = fmaxf(mt, sv);
        }

        // corr: exp(0)=1 when both -FLT_MAX; exp(-huge)=0 once real scores seen
        const float corr = __expf(m - mt);
        m = mt;
        l *= corr;
        #pragma unroll
        for (int d = 0; d < DH; d++) acc[d] *= corr;

        #pragma unroll
        for (int j = 0; j < KT; j++) {
            float p = __expf(s[j] - mt);
            l += p;
            const float4* vp = (const float4*)&vs[j][0];
            #pragma unroll
            for (int t = 0; t < DH / 4; t++) {
                float4 vv = vp[t];
                acc[4 * t + 0] += p * vv.x;
                acc[4 * t + 1] += p * vv.y;
                acc[4 * t + 2] += p * vv.z;
                acc[4 * t + 3] += p * vv.w;
            }
        }
    }

    const float inv = 1.0f / l;   // l >= 1 always (uniform fallback => l = 4096)
    #pragma unroll
    for (int d = 0; d < DH; d++)
        g_ao[qi * D_MODEL + base + d] = acc[d] * inv;
}

// ---------------------------------------------------------------------------
extern "C" void kernel_launch(void* const* d_in, const int* in_sizes, int n_in,
                              void* d_out, int out_size)
{
    const float* x   = (const float*)d_in[0];
    const float* gm  = (const float*)d_in[1];
    const float* Wq  = (const float*)d_in[2];
    const float* Wk  = (const float*)d_in[3];
    const float* Wv  = (const float*)d_in[4];
    const float* Wo  = (const float*)d_in[5];
    const float* bo  = (const float*)d_in[6];
    float* out = (float*)d_out;

    float *q, *k, *v, *ao;
    cudaGetSymbolAddress((void**)&q,  g_q);
    cudaGetSymbolAddress((void**)&k,  g_k);
    cudaGetSymbolAddress((void**)&v,  g_v);
    cudaGetSymbolAddress((void**)&ao, g_ao);

    dim3 gemm_grid(D_MODEL / 64, NQ / 64);  // (5, 64)

    gemm_kernel<<<gemm_grid, 256>>>(x, Wq, nullptr, q, NQ, D_MODEL, D_MODEL);
    gemm_kernel<<<gemm_grid, 256>>>(x, Wk, nullptr, k, NQ, D_MODEL, D_MODEL);
    gemm_kernel<<<gemm_grid, 256>>>(x, Wv, nullptr, v, NQ, D_MODEL, D_MODEL);

    mask_kernel<<<NQ / 256, 256>>>(gm);

    attn_kernel<<<dim3(NQ / QT, HEADS), QT>>>();

    gemm_kernel<<<gemm_grid, 256>>>(ao, Wo, bo, out, NQ, D_MODEL, D_MODEL);
}

// round 7
// speedup vs baseline: 1.0065x; 1.0019x over previous
#include <cuda_runtime.h>
#include <cfloat>

#define NQ      4096
#define D_MODEL 320
#define HEADS   8
#define DH      40
#define KT      32     // key tile
#define QT      128    // queries per block (1 thread per query)

// Scratch (static: no allocation allowed in kernel_launch)
__device__ float g_q[NQ * D_MODEL];
__device__ float g_k[NQ * D_MODEL];
__device__ float g_v[NQ * D_MODEL];
__device__ float g_ao[NQ * D_MODEL];
__device__ unsigned int g_bits[NQ];

// ---------------------------------------------------------------------------
// SGEMM: C[M,N] = A[M,K] @ B[K,N] (+ bias). 64x64 block tile, 16 K-tile,
// 256 threads, 4x4 register micro-tile. M,N,K assumed multiples of tile dims
// (4096/320/320 all are).
// ---------------------------------------------------------------------------
__global__ void __launch_bounds__(256) gemm_kernel(
    const float* __restrict__ A, const float* __restrict__ B,
    const float* __restrict__ bias, float* __restrict__ C,
    int M, int N, int K)
{
    __shared__ float As[16][64];   // transposed A tile: As[k][m]
    __shared__ float Bs[16][64];   // Bs[k][n]

    const int tid  = threadIdx.x;
    const int tx   = tid & 15;     // 0..15 -> 4 cols each
    const int ty   = tid >> 4;     // 0..15 -> 4 rows each
    const int row0 = blockIdx.y * 64;
    const int col0 = blockIdx.x * 64;

    const int a_m = tid >> 2;        // 0..63
    const int a_k = (tid & 3) * 4;   // 0,4,8,12
    const int b_k = tid >> 4;        // 0..15
    const int b_n = (tid & 15) * 4;  // 0..60

    float acc[4][4] = {};

    for (int k0 = 0; k0 < K; k0 += 16) {
        float4 av = *(const float4*)&A[(row0 + a_m) * K + k0 + a_k];
        As[a_k + 0][a_m] = av.x;
        As[a_k + 1][a_m] = av.y;
        As[a_k + 2][a_m] = av.z;
        As[a_k + 3][a_m] = av.w;
        *(float4*)&Bs[b_k][b_n] = *(const float4*)&B[(k0 + b_k) * N + col0 + b_n];
        __syncthreads();

        #pragma unroll
        for (int kk = 0; kk < 16; kk++) {
            float4 af = *(const float4*)&As[kk][ty * 4];
            float4 bf = *(const float4*)&Bs[kk][tx * 4];
            acc[0][0] += af.x * bf.x; acc[0][1] += af.x * bf.y;
            acc[0][2] += af.x * bf.z; acc[0][3] += af.x * bf.w;
            acc[1][0] += af.y * bf.x; acc[1][1] += af.y * bf.y;
            acc[1][2] += af.y * bf.z; acc[1][3] += af.y * bf.w;
            acc[2][0] += af.z * bf.x; acc[2][1] += af.z * bf.y;
            acc[2][2] += af.z * bf.z; acc[2][3] += af.z * bf.w;
            acc[3][0] += af.w * bf.x; acc[3][1] += af.w * bf.y;
            acc[3][2] += af.w * bf.z; acc[3][3] += af.w * bf.w;
        }
        __syncthreads();
    }

    #pragma unroll
    for (int i = 0; i < 4; i++) {
        const int r = row0 + ty * 4 + i;
        #pragma unroll
        for (int j = 0; j < 4; j++) {
            const int c = col0 + tx * 4 + j;
            float val = acc[i][j];
            if (bias) val += bias[c];
            C[r * N + c] = val;
        }
    }
}

// ---------------------------------------------------------------------------
// Pack guidance mask -> 3-bit phase occupancy per token.
// mask_sim[i][j] != 0  <=>  (bits[i] & bits[j]) != 0
// ---------------------------------------------------------------------------
__global__ void mask_kernel(const float* __restrict__ g)
{
    int i = blockIdx.x * blockDim.x + threadIdx.x;
    if (i < NQ) {
        unsigned int b = 0;
        if (g[0 * NQ + i] > 0.5f) b |= 1u;
        if (g[1 * NQ + i] > 0.5f) b |= 2u;
        if (g[2 * NQ + i] > 0.5f) b |= 4u;
        g_bits[i] = b;
    }
}

// ---------------------------------------------------------------------------
// Flash-style masked attention. One thread owns one query row of one head.
// Masked score = -FLT_MAX (NOT -inf): reproduces jax softmax's uniform
// distribution for fully-masked rows (exp(0)=1 everywhere).
// ---------------------------------------------------------------------------
__global__ void __launch_bounds__(QT) attn_kernel()
{
    const int h    = blockIdx.y;
    const int qi   = blockIdx.x * QT + threadIdx.x;
    const int base = h * DH;

    __shared__ float ks[KT][DH];
    __shared__ float vs[KT][DH];
    __shared__ unsigned int kb[KT];

    const float scale = 0.15811388300841897f;  // 40^-0.5

    float qr[DH];
    #pragma unroll
    for (int d = 0; d < DH; d++)
        qr[d] = g_q[qi * D_MODEL + base + d] * scale;
    const unsigned int qb = g_bits[qi];

    float m = -FLT_MAX;
    float l = 0.0f;
    float acc[DH];
    #pragma unroll
    for (int d = 0; d < DH; d++) acc[d] = 0.0f;

    for (int kt = 0; kt < NQ; kt += KT) {
        __syncthreads();
        #pragma unroll
        for (int t = 0; t < (KT * DH) / QT; t++) {
            int idx = threadIdx.x + t * QT;
            int j = idx / DH;
            int d = idx - j * DH;
            ks[j][d] = g_k[(kt + j) * D_MODEL + base + d];
            vs[j][d] = g_v[(kt + j) * D_MODEL + base + d];
        }
        if (threadIdx.x < KT) kb[threadIdx.x] = g_bits[kt + threadIdx.x];
        __syncthreads();

        float s[KT];
        float mt = m;
        #pragma unroll
        for (int j = 0; j < KT; j++) {
            const float4* kp = (const float4*)&ks[j][0];
            float a0 = 0.f, a1 = 0.f, a2 = 0.f, a3 = 0.f;
            #pragma unroll
            for (int t = 0; t < DH / 4; t++) {
                float4 kk = kp[t];
                a0 += qr[4 * t + 0] * kk.x;
                a1 += qr[4 * t + 1] * kk.y;
                a2 += qr[4 * t + 2] * kk.z;
                a3 += qr[4 * t + 3] * kk.w;
            }
            float sv = (a0 + a1) + (a2 + a3);
            sv = (qb & kb[j]) ? sv : -FLT_MAX;
            s[j] = sv;
            mt = fmaxf(mt, sv);
        }

        // corr: exp(0)=1 when both -FLT_MAX; exp(-huge)=0 once real scores seen
        const float corr = __expf(m - mt);
        m = mt;
        l *= corr;
        #pragma unroll
        for (int d = 0; d < DH; d++) acc[d] *= corr;

        #pragma unroll
        for (int j = 0; j < KT; j++) {
            float p = __expf(s[j] - mt);
            l += p;
            const float4* vp = (const float4*)&vs[j][0];
            #pragma unroll
            for (int t = 0; t < DH / 4; t++) {
                float4 vv = vp[t];
                acc[4 * t + 0] += p * vv.x;
                acc[4 * t + 1] += p * vv.y;
                acc[4 * t + 2] += p * vv.z;
                acc[4 * t + 3] += p * vv.w;
            }
        }
    }

    const float inv = 1.0f / l;   // l >= 1 always (uniform fallback => l = 4096)
    #pragma unroll
    for (int d = 0; d < DH; d++)
        g_ao[qi * D_MODEL + base + d] = acc[d] * inv;
}

// ---------------------------------------------------------------------------
extern "C" void kernel_launch(void* const* d_in, const int* in_sizes, int n_in,
                              void* d_out, int out_size)
{
    const float* x   = (const float*)d_in[0];
    const float* gm  = (const float*)d_in[1];
    const float* Wq  = (const float*)d_in[2];
    const float* Wk  = (const float*)d_in[3];
    const float* Wv  = (const float*)d_in[4];
    const float* Wo  = (const float*)d_in[5];
    const float* bo  = (const float*)d_in[6];
    float* out = (float*)d_out;

    float *q, *k, *v, *ao;
    cudaGetSymbolAddress((void**)&q,  g_q);
    cudaGetSymbolAddress((void**)&k,  g_k);
    cudaGetSymbolAddress((void**)&v,  g_v);
    cudaGetSymbolAddress((void**)&ao, g_ao);

    dim3 gemm_grid(D_MODEL / 64, NQ / 64);  // (5, 64)

    gemm_kernel<<<gemm_grid, 256>>>(x, Wq, nullptr, q, NQ, D_MODEL, D_MODEL);
    gemm_kernel<<<gemm_grid, 256>>>(x, Wk, nullptr, k, NQ, D_MODEL, D_MODEL);
    gemm_kernel<<<gemm_grid, 256>>>(x, Wv, nullptr, v, NQ, D_MODEL, D_MODEL);

    mask_kernel<<<NQ / 256, 256>>>(gm);

    attn_kernel<<<dim3(NQ / QT, HEADS), QT>>>();

    gemm_kernel<<<gemm_grid, 256>>>(ao, Wo, bo, out, NQ, D_MODEL, D_MODEL);
}

// round 8
// speedup vs baseline: 1.0077x; 1.0012x over previous
#include <cuda_runtime.h>
#include <cfloat>

#define NQ      4096
#define D_MODEL 320
#define HEADS   8
#define DH      40
#define KT      32     // key tile
#define QT      128    // queries per block (1 thread per query)

// Scratch (static: no allocation allowed in kernel_launch)
__device__ float g_q[NQ * D_MODEL];
__device__ float g_k[NQ * D_MODEL];
__device__ float g_v[NQ * D_MODEL];
__device__ float g_ao[NQ * D_MODEL];
__device__ unsigned int g_bits[NQ];

// ---------------------------------------------------------------------------
// SGEMM: C[M,N] = A[M,K] @ B[K,N] (+ bias). 64x64 block tile, 16 K-tile,
// 256 threads, 4x4 register micro-tile. M,N,K assumed multiples of tile dims
// (4096/320/320 all are).
// ---------------------------------------------------------------------------
__global__ void __launch_bounds__(256) gemm_kernel(
    const float* __restrict__ A, const float* __restrict__ B,
    const float* __restrict__ bias, float* __restrict__ C,
    int M, int N, int K)
{
    __shared__ float As[16][64];   // transposed A tile: As[k][m]
    __shared__ float Bs[16][64];   // Bs[k][n]

    const int tid  = threadIdx.x;
    const int tx   = tid & 15;     // 0..15 -> 4 cols each
    const int ty   = tid >> 4;     // 0..15 -> 4 rows each
    const int row0 = blockIdx.y * 64;
    const int col0 = blockIdx.x * 64;

    const int a_m = tid >> 2;        // 0..63
    const int a_k = (tid & 3) * 4;   // 0,4,8,12
    const int b_k = tid >> 4;        // 0..15
    const int b_n = (tid & 15) * 4;  // 0..60

    float acc[4][4] = {};

    for (int k0 = 0; k0 < K; k0 += 16) {
        float4 av = *(const float4*)&A[(row0 + a_m) * K + k0 + a_k];
        As[a_k + 0][a_m] = av.x;
        As[a_k + 1][a_m] = av.y;
        As[a_k + 2][a_m] = av.z;
        As[a_k + 3][a_m] = av.w;
        *(float4*)&Bs[b_k][b_n] = *(const float4*)&B[(k0 + b_k) * N + col0 + b_n];
        __syncthreads();

        #pragma unroll
        for (int kk = 0; kk < 16; kk++) {
            float4 af = *(const float4*)&As[kk][ty * 4];
            float4 bf = *(const float4*)&Bs[kk][tx * 4];
            acc[0][0] += af.x * bf.x; acc[0][1] += af.x * bf.y;
            acc[0][2] += af.x * bf.z; acc[0][3] += af.x * bf.w;
            acc[1][0] += af.y * bf.x; acc[1][1] += af.y * bf.y;
            acc[1][2] += af.y * bf.z; acc[1][3] += af.y * bf.w;
            acc[2][0] += af.z * bf.x; acc[2][1] += af.z * bf.y;
            acc[2][2] += af.z * bf.z; acc[2][3] += af.z * bf.w;
            acc[3][0] += af.w * bf.x; acc[3][1] += af.w * bf.y;
            acc[3][2] += af.w * bf.z; acc[3][3] += af.w * bf.w;
        }
        __syncthreads();
    }

    #pragma unroll
    for (int i = 0; i < 4; i++) {
        const int r = row0 + ty * 4 + i;
        #pragma unroll
        for (int j = 0; j < 4; j++) {
            const int c = col0 + tx * 4 + j;
            float val = acc[i][j];
            if (bias) val += bias[c];
            C[r * N + c] = val;
        }
    }
}

// ---------------------------------------------------------------------------
// Pack guidance mask -> 3-bit phase occupancy per token.
// mask_sim[i][j] != 0  <=>  (bits[i] & bits[j]) != 0
// ---------------------------------------------------------------------------
__global__ void mask_kernel(const float* __restrict__ g)
{
    int i = blockIdx.x * blockDim.x + threadIdx.x;
    if (i < NQ) {
        unsigned int b = 0;
        if (g[0 * NQ + i] > 0.5f) b |= 1u;
        if (g[1 * NQ + i] > 0.5f) b |= 2u;
        if (g[2 * NQ + i] > 0.5f) b |= 4u;
        g_bits[i] = b;
    }
}

// ---------------------------------------------------------------------------
// Flash-style masked attention. One thread owns one query row of one head.
// Masked score = -FLT_MAX (NOT -inf): reproduces jax softmax's uniform
// distribution for fully-masked rows (exp(0)=1 everywhere).
// ---------------------------------------------------------------------------
__global__ void __launch_bounds__(QT) attn_kernel()
{
    const int h    = blockIdx.y;
    const int qi   = blockIdx.x * QT + threadIdx.x;
    const int base = h * DH;

    __shared__ float ks[KT][DH];
    __shared__ float vs[KT][DH];
    __shared__ unsigned int kb[KT];

    const float scale = 0.15811388300841897f;  // 40^-0.5

    float qr[DH];
    #pragma unroll
    for (int d = 0; d < DH; d++)
        qr[d] = g_q[qi * D_MODEL + base + d] * scale;
    const unsigned int qb = g_bits[qi];

    float m = -FLT_MAX;
    float l = 0.0f;
    float acc[DH];
    #pragma unroll
    for (int d = 0; d < DH; d++) acc[d] = 0.0f;

    for (int kt = 0; kt < NQ; kt += KT) {
        __syncthreads();
        #pragma unroll
        for (int t = 0; t < (KT * DH) / QT; t++) {
            int idx = threadIdx.x + t * QT;
            int j = idx / DH;
            int d = idx - j * DH;
            ks[j][d] = g_k[(kt + j) * D_MODEL + base + d];
            vs[j][d] = g_v[(kt + j) * D_MODEL + base + d];
        }
        if (threadIdx.x < KT) kb[threadIdx.x] = g_bits[kt + threadIdx.x];
        __syncthreads();

        float s[KT];
        float mt = m;
        #pragma unroll
        for (int j = 0; j < KT; j++) {
            const float4* kp = (const float4*)&ks[j][0];
            float a0 = 0.f, a1 = 0.f, a2 = 0.f, a3 = 0.f;
            #pragma unroll
            for (int t = 0; t < DH / 4; t++) {
                float4 kk = kp[t];
                a0 += qr[4 * t + 0] * kk.x;
                a1 += qr[4 * t + 1] * kk.y;
                a2 += qr[4 * t + 2] * kk.z;
                a3 += qr[4 * t + 3] * kk.w;
            }
            float sv = (a0 + a1) + (a2 + a3);
            sv = (qb & kb[j]) ? sv : -FLT_MAX;
            s[j] = sv;
            mt = fmaxf(mt, sv);
        }

        // corr: exp(0)=1 when both -FLT_MAX; exp(-huge)=0 once real scores seen
        const float corr = __expf(m - mt);
        m = mt;
        l *= corr;
        #pragma unroll
        for (int d = 0; d < DH; d++) acc[d] *= corr;

        #pragma unroll
        for (int j = 0; j < KT; j++) {
            float p = __expf(s[j] - mt);
            l += p;
            const float4* vp = (const float4*)&vs[j][0];
            #pragma unroll
            for (int t = 0; t < DH / 4; t++) {
                float4 vv = vp[t];
                acc[4 * t + 0] += p * vv.x;
                acc[4 * t + 1] += p * vv.y;
                acc[4 * t + 2] += p * vv.z;
                acc[4 * t + 3] += p * vv.w;
            }
        }
    }

    const float inv = 1.0f / l;   // l >= 1 always (uniform fallback => l = 4096)
    #pragma unroll
    for (int d = 0; d < DH; d++)
        g_ao[qi * D_MODEL + base + d] = acc[d] * inv;
}

// ---------------------------------------------------------------------------
extern "C" void kernel_launch(void* const* d_in, const int* in_sizes, int n_in,
                              void* d_out, int out_size)
{
    const float* x   = (const float*)d_in[0];
    const float* gm  = (const float*)d_in[1];
    const float* Wq  = (const float*)d_in[2];
    const float* Wk  = (const float*)d_in[3];
    const float* Wv  = (const float*)d_in[4];
    const float* Wo  = (const float*)d_in[5];
    const float* bo  = (const float*)d_in[6];
    float* out = (float*)d_out;

    float *q, *k, *v, *ao;
    cudaGetSymbolAddress((void**)&q,  g_q);
    cudaGetSymbolAddress((void**)&k,  g_k);
    cudaGetSymbolAddress((void**)&v,  g_v);
    cudaGetSymbolAddress((void**)&ao, g_ao);

    dim3 gemm_grid(D_MODEL / 64, NQ / 64);  // (5, 64)

    gemm_kernel<<<gemm_grid, 256>>>(x, Wq, nullptr, q, NQ, D_MODEL, D_MODEL);
    gemm_kernel<<<gemm_grid, 256>>>(x, Wk, nullptr, k, NQ, D_MODEL, D_MODEL);
    gemm_kernel<<<gemm_grid, 256>>>(x, Wv, nullptr, v, NQ, D_MODEL, D_MODEL);

    mask_kernel<<<NQ / 256, 256>>>(gm);

    attn_kernel<<<dim3(NQ / QT, HEADS), QT>>>();

    gemm_kernel<<<gemm_grid, 256>>>(ao, Wo, bo, out, NQ, D_MODEL, D_MODEL);
}